// round 1
// baseline (speedup 1.0000x reference)
#include <cuda_runtime.h>
#include <math.h>

#define NH 76
#define NW 76
#define NA 3
#define NCLS 80
#define NATTR (5 + NCLS)
#define MAXT 64
#define MAXB 32
#define CELLS (NA * NH * NW)
#define HW (NH * NW)

struct GT {
    float bx1, bx2, by1, by2, areaB;   // gt box corners + area (grid units)
    float txv, tyv, twv, thv, coord;   // regression targets
    int   gi, gj, aloc, cls, valid, pad;
};

__device__ GT     g_gt[MAXB * MAXT];
__device__ double g_acc;

__constant__ float c_anch[18] = {10.f,13.f, 16.f,30.f, 33.f,23.f, 30.f,61.f, 62.f,45.f,
                                 59.f,119.f, 116.f,90.f, 156.f,198.f, 373.f,326.f};

__device__ __forceinline__ float read_dim(const void* p) {
    int iv = *(const int*)p;
    if (iv > 0 && iv < 1000000) return (float)iv;      // int32 (or LE int64) scalar
    float fv = *(const float*)p;
    if (fv >= 1.0f && fv < 1.0e6f) return fv;          // float32 scalar
    return 608.0f;                                     // fallback (known setup)
}

// ---------------- Phase A: per-GT precompute (+ zero accumulator) ----------------
__global__ void yolo_phaseA(const float* __restrict__ target, const void* dimp,
                            int nB, int nT) {
    int b = blockIdx.x;
    int t = threadIdx.x;
    if (b == 0 && t == 0) g_acc = 0.0;

    __shared__ int nz[MAXT];
    float img  = read_dim(dimp);
    float invs = (float)NH / img;     // 1 / stride

    float t0 = 0.f, t1 = 0.f, t2 = 0.f, t3 = 0.f, t4 = 0.f;
    if (t < nT) {
        const float* tg = target + ((size_t)b * nT + t) * 5;
        t0 = tg[0]; t1 = tg[1]; t2 = tg[2]; t3 = tg[3]; t4 = tg[4];
        float s = t0 + t1 + t2 + t3 + t4;
        nz[t] = (s != 0.0f) ? 1 : 0;
    }
    __syncthreads();
    if (t >= nT) return;

    int valid = 1;
    for (int q = 0; q <= t; q++) valid &= nz[q];

    float gx = t1 * NW, gy = t2 * NH, gw = t3 * NW, gh = t4 * NH;
    int gi = min(max((int)gx, 0), NW - 1);
    int gj = min(max((int)gy, 0), NH - 1);

    // best anchor over all 9 (shape-only IoU); first max wins (JAX argmax)
    int best = 0; float bestr = -1.0f;
    for (int k = 0; k < 9; k++) {
        float aw = c_anch[2*k] * invs, ah = c_anch[2*k+1] * invs;
        float inter = fminf(gw, aw) * fminf(gh, ah);
        float uni   = gw * gh + aw * ah - inter;
        float r = inter / (uni + 1e-16f);
        if (r > bestr) { bestr = r; best = k; }
    }
    int aloc = (best < NA) ? best : -1;   // mask = [0,1,2]

    GT g;
    g.bx1 = gx - 0.5f * gw; g.bx2 = gx + 0.5f * gw;
    g.by1 = gy - 0.5f * gh; g.by2 = gy + 0.5f * gh;
    g.areaB = gw * gh;
    g.valid = valid;
    g.gi = gi; g.gj = gj;
    g.aloc = (valid && aloc >= 0) ? aloc : -1;  // -1 => never matches a cell
    g.txv = gx - (float)gi;
    g.tyv = gy - (float)gj;
    int al = max(aloc, 0);
    g.twv = logf(gw / (c_anch[2*al]   * invs) + 1e-16f);
    g.thv = logf(gh / (c_anch[2*al+1] * invs) + 1e-16f);
    g.coord = sqrtf(2.0f - t3 * t4);
    g.cls = min(max((int)t0, 0), NCLS - 1);
    g.pad = 0;
    g_gt[b * MAXT + t] = g;
}

// ---------------- Phase B: per-cell loss ----------------
__global__ void __launch_bounds__(256) yolo_main(const float* __restrict__ x,
                                                 const void* dimp, int nT) {
    int b = blockIdx.y;
    int cell = blockIdx.x * 256 + threadIdx.x;

    __shared__ GT s_gt[MAXT];
    __shared__ double ws[8];
    for (int r = threadIdx.x; r < nT; r += 256) s_gt[r] = g_gt[b * MAXT + r];
    __syncthreads();

    double loss = 0.0;
    if (cell < CELLS) {
        int a   = cell / HW;
        int rem = cell - a * HW;
        int j = rem / NW, i = rem - j * NW;

        const float* xb = x + ((size_t)b * (NA * NATTR) + a * NATTR) * HW + rem;
        float x0 = xb[0], x1 = xb[HW], x2 = xb[2*HW], x3 = xb[3*HW], x4 = xb[4*HW];

        float img  = read_dim(dimp);
        float invs = (float)NH / img;
        float aw = c_anch[2*a] * invs, ah = c_anch[2*a+1] * invs;

        float sx = 1.f / (1.f + expf(-x0));
        float sy = 1.f / (1.f + expf(-x1));
        float pw = expf(x2) * aw;
        float ph = expf(x3) * ah;
        float cx = sx + (float)i, cy = sy + (float)j;
        float ax1 = cx - 0.5f * pw, ax2 = cx + 0.5f * pw;
        float ay1 = cy - 0.5f * ph, ay2 = cy + 0.5f * ph;
        float areaA = pw * ph;

        bool noobj = true;
        int  win   = -1;
        for (int t = 0; t < nT; t++) {
            const GT& g = s_gt[t];
            if (g.valid) {
                float iw = fmaxf(fminf(ax2, g.bx2) - fmaxf(ax1, g.bx1), 0.f);
                float ih = fmaxf(fminf(ay2, g.by2) - fmaxf(ay1, g.by1), 0.f);
                float inter = iw * ih;
                float uni = areaA + g.areaB - inter;
                if (inter > 0.7f * (uni + 1e-16f)) noobj = false;
                if (g.aloc == a && g.gi == i && g.gj == j) win = t;  // last t wins
            }
        }

        float conf = 1.f / (1.f + expf(-x4));
        if (noobj) loss += -(double)logf(1.f - conf + 1e-12f);

        if (win >= 0) {
            const GT& g = s_gt[win];
            loss += -(double)logf(conf + 1e-12f);
            float m2 = g.coord * g.coord;
            float dx = sx - g.txv, dy = sy - g.tyv;
            float dw = x2 - g.twv, dh = x3 - g.thv;
            loss += 0.5 * (double)(m2 * (dx*dx + dy*dy + dw*dw + dh*dh));
            for (int c = 0; c < NCLS; c++) {
                float pc = 1.f / (1.f + expf(-xb[(5 + c) * HW]));
                float arg = (c == g.cls) ? pc : (1.f - pc);
                loss += -(double)logf(arg + 1e-12f);
            }
        }
    }

    // block reduction (double)
    int lane = threadIdx.x & 31, wid = threadIdx.x >> 5;
    #pragma unroll
    for (int o = 16; o > 0; o >>= 1) loss += __shfl_down_sync(0xffffffffu, loss, o);
    if (lane == 0) ws[wid] = loss;
    __syncthreads();
    if (wid == 0) {
        double v = (lane < 8) ? ws[lane] : 0.0;
        #pragma unroll
        for (int o = 4; o > 0; o >>= 1) v += __shfl_down_sync(0xffffffffu, v, o);
        if (lane == 0) atomicAdd(&g_acc, v);
    }
}

__global__ void yolo_fin(float* out) { out[0] = (float)g_acc; }

extern "C" void kernel_launch(void* const* d_in, const int* in_sizes, int n_in,
                              void* d_out, int out_size) {
    const float* x      = (const float*)d_in[0];
    const float* target = (const float*)d_in[1];
    const void*  dimp   = (n_in > 2) ? d_in[2] : nullptr;

    int nB = in_sizes[0] / (NA * NATTR * NH * NW);
    if (nB < 1) nB = 1;
    if (nB > MAXB) nB = MAXB;
    int nT = in_sizes[1] / (nB * 5);
    if (nT > MAXT) nT = MAXT;

    yolo_phaseA<<<nB, MAXT>>>(target, dimp, nB, nT);
    dim3 grid((CELLS + 255) / 256, nB);
    yolo_main<<<grid, 256>>>(x, dimp, nT);
    yolo_fin<<<1, 1>>>((float*)d_out);
}

// round 2
// speedup vs baseline: 1.7018x; 1.7018x over previous
#include <cuda_runtime.h>
#include <math.h>

#define NH 76
#define NW 76
#define NA 3
#define NCLS 80
#define NATTR 85
#define MAXT 64
#define CELLS (NA * NH * NW)   // 17328
#define HW (NH * NW)           // 5776
#define TPB 256
#define BLKX ((CELLS + TPB - 1) / TPB)   // 68

__device__ double   g_acc;   // zero-init at module load; reset by last block each launch
__device__ unsigned g_cnt;

__constant__ float c_anch[18] = {10.f,13.f, 16.f,30.f, 33.f,23.f, 30.f,61.f, 62.f,45.f,
                                 59.f,119.f, 116.f,90.f, 156.f,198.f, 373.f,326.f};

__device__ __forceinline__ float read_dim(const void* p) {
    if (p == nullptr) return 608.0f;
    int iv = *(const int*)p;
    if (iv > 0 && iv < 1000000) return (float)iv;
    float fv = *(const float*)p;
    if (fv >= 1.0f && fv < 1.0e6f) return fv;
    return 608.0f;
}

__device__ __forceinline__ float fsig(float v) {
    return __fdividef(1.0f, 1.0f + __expf(-v));
}

__global__ void __launch_bounds__(TPB)
yolo_fused(const float* __restrict__ x, const float* __restrict__ target,
           const void* dimp, int nB, int nT, float* __restrict__ out,
           int nBlocksTotal)
{
    __shared__ float s_bx1[MAXT], s_bx2[MAXT], s_by1[MAXT], s_by2[MAXT], s_kb[MAXT];
    __shared__ float s_tx[MAXT], s_ty[MAXT], s_tw[MAXT], s_th[MAXT], s_m2[MAXT];
    __shared__ int   s_cell[MAXT], s_cls[MAXT], s_nz[MAXT];
    __shared__ int   s_V;
    __shared__ double ws[TPB / 32];

    const int b   = blockIdx.y;
    const int tid = threadIdx.x;
    const float img  = read_dim(dimp);
    const float invs = (float)NH / img;   // 1/stride

    // ---- per-block GT precompute (redundant across blocks; cheap) ----
    float t0 = 0.f, t1 = 0.f, t2 = 0.f, t3 = 0.f, t4 = 0.f;
    if (tid < nT) {
        const float* tg = target + ((size_t)b * nT + tid) * 5;
        t0 = tg[0]; t1 = tg[1]; t2 = tg[2]; t3 = tg[3]; t4 = tg[4];
        s_nz[tid] = ((t0 + t1 + t2 + t3 + t4) != 0.0f) ? 1 : 0;
    }
    __syncthreads();
    if (tid == 0) {                       // validity is a cumprod => prefix length V
        int V = 0;
        while (V < nT && s_nz[V]) V++;
        s_V = V;
    }
    __syncthreads();

    if (tid < nT) {
        const int valid = (tid < s_V);
        float gx = t1 * NW, gy = t2 * NH, gw = t3 * NW, gh = t4 * NH;
        int gi = min(max((int)gx, 0), NW - 1);
        int gj = min(max((int)gy, 0), NH - 1);

        int best = 0; float bestr = -1.0f;
        #pragma unroll
        for (int k = 0; k < 9; k++) {
            float aw = c_anch[2*k] * invs, ah = c_anch[2*k+1] * invs;
            float inter = fminf(gw, aw) * fminf(gh, ah);
            float uni   = gw * gh + aw * ah - inter;
            float r = __fdividef(inter, uni + 1e-16f);
            if (r > bestr) { bestr = r; best = k; }
        }
        int aloc = (best < NA) ? best : -1;     // mask = [0,1,2]

        s_bx1[tid] = gx - 0.5f * gw;  s_bx2[tid] = gx + 0.5f * gw;
        s_by1[tid] = gy - 0.5f * gh;  s_by2[tid] = gy + 0.5f * gh;
        s_kb[tid]  = valid ? (7.0f / 17.0f) * (gw * gh) : 3.0e38f;  // invalid never ignores
        s_cell[tid] = (valid && aloc >= 0) ? (aloc * HW + gj * NW + gi) : -1;
        s_tx[tid] = gx - (float)gi;
        s_ty[tid] = gy - (float)gj;
        int al = max(aloc, 0);
        s_tw[tid] = __logf(__fdividef(gw, c_anch[2*al]   * invs) + 1e-16f);
        s_th[tid] = __logf(__fdividef(gh, c_anch[2*al+1] * invs) + 1e-16f);
        s_m2[tid] = 2.0f - t3 * t4;            // coord^2, no sqrt needed
        s_cls[tid] = min(max((int)t0, 0), NCLS - 1);
    }
    __syncthreads();

    // ---- per-cell loss ----
    const int cell = blockIdx.x * TPB + tid;
    float loss = 0.0f;
    if (cell < CELLS) {
        const int a   = cell / HW;
        const int rem = cell - a * HW;
        const int j = rem / NW, i = rem - j * NW;

        const float* xb = x + ((size_t)b * (NA * NATTR) + (size_t)a * NATTR) * HW + rem;
        const float x0 = xb[0];
        const float x1 = xb[(size_t)HW];
        const float x2 = xb[2 * (size_t)HW];
        const float x3 = xb[3 * (size_t)HW];
        const float x4 = xb[4 * (size_t)HW];

        const float aw = c_anch[2*a] * invs, ah = c_anch[2*a+1] * invs;
        const float sx = fsig(x0), sy = fsig(x1);
        const float pw = __expf(x2) * aw, ph = __expf(x3) * ah;
        const float cx = sx + (float)i, cy = sy + (float)j;
        const float ax1 = cx - 0.5f * pw, ax2 = cx + 0.5f * pw;
        const float ay1 = cy - 0.5f * ph, ay2 = cy + 0.5f * ph;
        const float base = (7.0f / 17.0f) * (pw * ph + 1e-16f);

        const int V = s_V;
        bool ignore = false;
        int  win = -1;
        #pragma unroll 2
        for (int t = 0; t < V; t++) {
            float iw = fminf(ax2, s_bx2[t]) - fmaxf(ax1, s_bx1[t]);
            float ih = fminf(ay2, s_by2[t]) - fmaxf(ay1, s_by1[t]);
            iw = fmaxf(iw, 0.0f); ih = fmaxf(ih, 0.0f);
            float inter = iw * ih;
            ignore = ignore || (inter > base + s_kb[t]);
            win = (s_cell[t] == cell) ? t : win;          // last t wins (scatter .set)
        }

        const float conf = fsig(x4);
        if (!ignore) loss -= __logf(1.0f - conf + 1e-12f);

        if (win >= 0) {
            loss -= __logf(conf + 1e-12f);
            const float dx = sx - s_tx[win], dy = sy - s_ty[win];
            const float dw = x2 - s_tw[win], dh = x3 - s_th[win];
            loss += 0.5f * s_m2[win] * (dx*dx + dy*dy + dw*dw + dh*dh);
            const int cc = s_cls[win];
            #pragma unroll 4
            for (int c = 0; c < NCLS; c++) {
                float pc = fsig(xb[(size_t)(5 + c) * HW]);
                float arg = (c == cc) ? pc : (1.0f - pc);
                loss -= __logf(arg + 1e-12f);
            }
        }
    }

    // ---- reduction: warp f32 -> block f64 -> global atomic f64 ----
    const int lane = tid & 31, wid = tid >> 5;
    #pragma unroll
    for (int o = 16; o > 0; o >>= 1) loss += __shfl_down_sync(0xffffffffu, loss, o);
    if (lane == 0) ws[wid] = (double)loss;
    __syncthreads();
    if (wid == 0) {
        double v = (lane < TPB / 32) ? ws[lane] : 0.0;
        #pragma unroll
        for (int o = 4; o > 0; o >>= 1) v += __shfl_down_sync(0xffffffffu, v, o);
        if (lane == 0) {
            atomicAdd(&g_acc, v);
            __threadfence();
            unsigned done = atomicInc(&g_cnt, 0xffffffffu);
            if (done == (unsigned)(nBlocksTotal - 1)) {
                __threadfence();
                double r = *((volatile double*)&g_acc);
                out[0] = (float)r;
                g_acc = 0.0;          // reset for next graph replay
                g_cnt = 0u;
            }
        }
    }
}

extern "C" void kernel_launch(void* const* d_in, const int* in_sizes, int n_in,
                              void* d_out, int out_size) {
    const float* x      = (const float*)d_in[0];
    const float* target = (const float*)d_in[1];
    const void*  dimp   = (n_in > 2) ? d_in[2] : nullptr;

    int nB = in_sizes[0] / (NA * NATTR * NH * NW);
    if (nB < 1) nB = 1;
    int nT = in_sizes[1] / (nB * 5);
    if (nT > MAXT) nT = MAXT;
    if (nT < 1) nT = 1;

    dim3 grid(BLKX, nB);
    yolo_fused<<<grid, TPB>>>(x, target, dimp, nB, nT, (float*)d_out,
                              (int)(BLKX * nB));
}

// round 4
// speedup vs baseline: 2.1348x; 1.2545x over previous
#include <cuda_runtime.h>
#include <math.h>

#define NH 76
#define NW 76
#define NA 3
#define NCLS 80
#define NATTR 85
#define MAXT 64
#define CELLS (NA * NH * NW)   // 17328
#define HW (NH * NW)           // 5776
#define TPB 256
#define BLKX ((CELLS + TPB - 1) / TPB)   // 68

__device__ double   g_acc;
__device__ unsigned g_cnt;

__constant__ float c_anch[18] = {10.f,13.f, 16.f,30.f, 33.f,23.f, 30.f,61.f, 62.f,45.f,
                                 59.f,119.f, 116.f,90.f, 156.f,198.f, 373.f,326.f};

__device__ __forceinline__ float read_dim(const void* p) {
    if (p == nullptr) return 608.0f;
    int iv = *(const int*)p;
    if (iv > 0 && iv < 1000000) return (float)iv;
    float fv = *(const float*)p;
    if (fv >= 1.0f && fv < 1.0e6f) return fv;
    return 608.0f;
}

__global__ void __launch_bounds__(TPB, 8)
yolo_fused(const float* __restrict__ x, const float* __restrict__ target,
           const void* dimp, int nT, float* __restrict__ out, int nBlocksTotal)
{
    __shared__ float4 s_box[MAXT];                 // bx1, by1, bx2, by2
    __shared__ float  s_kb[MAXT];                  // (7/17) * areaB
    __shared__ float  s_tx[MAXT], s_ty[MAXT], s_tw[MAXT], s_th[MAXT], s_m2[MAXT];
    __shared__ int    s_cls[MAXT], s_nz[MAXT];
    __shared__ int    s_win[TPB];
    __shared__ int    s_V;
    __shared__ double ws[TPB / 32];

    const int b   = blockIdx.y;
    const int tid = threadIdx.x;
    const int blockStart = blockIdx.x * TPB;
    const float img  = read_dim(dimp);
    const float invs = (float)NH / img;            // 1/stride

    s_win[tid] = -1;

    // ---- per-block GT precompute (redundant across blocks; cheap) ----
    float t0 = 0.f, t1 = 0.f, t2 = 0.f, t3 = 0.f, t4 = 0.f;
    if (tid < nT) {
        const float* tg = target + ((size_t)b * nT + tid) * 5;
        t0 = tg[0]; t1 = tg[1]; t2 = tg[2]; t3 = tg[3]; t4 = tg[4];
        s_nz[tid] = ((t0 + t1 + t2 + t3 + t4) != 0.0f) ? 1 : 0;
    }
    __syncthreads();
    if (tid == 0) {                                // validity = cumprod => prefix length
        int V = 0;
        while (V < nT && s_nz[V]) V++;
        s_V = V;
    }
    __syncthreads();

    if (tid < s_V) {                               // only valid GTs participate
        float gx = t1 * NW, gy = t2 * NH, gw = t3 * NW, gh = t4 * NH;
        int gi = min(max((int)gx, 0), NW - 1);
        int gj = min(max((int)gy, 0), NH - 1);

        int best = 0; float bestr = -1.0f;
        #pragma unroll
        for (int k = 0; k < 9; k++) {
            float aw = c_anch[2*k] * invs, ah = c_anch[2*k+1] * invs;
            float inter = fminf(gw, aw) * fminf(gh, ah);
            float uni   = gw * gh + aw * ah - inter;
            float r = __fdividef(inter, uni + 1e-16f);
            if (r > bestr) { bestr = r; best = k; }
        }
        int aloc = (best < NA) ? best : -1;        // mask = [0,1,2]

        s_box[tid] = make_float4(gx - 0.5f * gw, gy - 0.5f * gh,
                                 gx + 0.5f * gw, gy + 0.5f * gh);
        s_kb[tid]  = (7.0f / 17.0f) * (gw * gh);
        s_tx[tid] = gx - (float)gi;
        s_ty[tid] = gy - (float)gj;
        int al = max(aloc, 0);
        s_tw[tid] = __logf(__fdividef(gw, c_anch[2*al]   * invs) + 1e-16f);
        s_th[tid] = __logf(__fdividef(gh, c_anch[2*al+1] * invs) + 1e-16f);
        s_m2[tid] = 2.0f - t3 * t4;                // coord^2 (sqrt^2 folds away)
        s_cls[tid] = min(max((int)t0, 0), NCLS - 1);

        if (aloc >= 0) {
            int cellid = aloc * HW + gj * NW + gi;
            int idx = cellid - blockStart;
            if (idx >= 0 && idx < TPB)
                atomicMax(&s_win[idx], tid);       // max-t == last-t-wins scatter
        }
    }
    __syncthreads();

    // ---- per-cell loss ----
    const int cell = blockStart + tid;
    float loss = 0.0f;
    if (cell < CELLS) {
        const int a   = cell / HW;
        const int rem = cell - a * HW;
        const int j = rem / NW, i = rem - j * NW;

        const float* xb = x + ((size_t)b * (NA * NATTR) + (size_t)a * NATTR) * HW + rem;
        const float x0 = xb[0];
        const float x1 = xb[(size_t)HW];
        const float x2 = xb[2 * (size_t)HW];
        const float x3 = xb[3 * (size_t)HW];
        const float x4 = xb[4 * (size_t)HW];

        const float aw = c_anch[2*a] * invs, ah = c_anch[2*a+1] * invs;
        const float sx = __fdividef(1.0f, 1.0f + __expf(-x0));
        const float sy = __fdividef(1.0f, 1.0f + __expf(-x1));
        const float pw = __expf(x2) * aw, ph = __expf(x3) * ah;
        const float cx = sx + (float)i, cy = sy + (float)j;
        const float ax1 = cx - 0.5f * pw, ax2 = cx + 0.5f * pw;
        const float ay1 = cy - 0.5f * ph, ay2 = cy + 0.5f * ph;
        const float base = (7.0f / 17.0f) * (pw * ph + 1e-16f);

        const int V = s_V;
        float ign = -1.0f;
        #pragma unroll 4
        for (int t = 0; t < V; t++) {
            const float4 bb = s_box[t];
            float iw = fminf(ax2, bb.z) - fmaxf(ax1, bb.x);
            float ih = fminf(ay2, bb.w) - fmaxf(ay1, bb.y);
            iw = fmaxf(iw, 0.0f); ih = fmaxf(ih, 0.0f);
            ign = fmaxf(ign, iw * ih - (base + s_kb[t]));
        }

        // noobj BCE: -log(1 - sigmoid(x4) + eps) ~= log(1 + e^{x4})
        const float softp = __logf(1.0f + __expf(x4));
        if (!(ign > 0.0f)) loss += softp;

        const int win = s_win[tid];
        if (win >= 0) {
            loss += softp - x4;                    // -log(sigmoid(x4)) = softp - x4
            const float dx = sx - s_tx[win], dy = sy - s_ty[win];
            const float dw = x2 - s_tw[win], dh = x3 - s_th[win];
            loss += 0.5f * s_m2[win] * (dx*dx + dy*dy + dw*dw + dh*dh);
            const int cc = s_cls[win];
            #pragma unroll 4
            for (int c = 0; c < NCLS; c++) {
                const float v = xb[(size_t)(5 + c) * HW];
                float lc = __logf(1.0f + __expf(v));   // -log(1 - sig(v) + eps)
                loss += (c == cc) ? (lc - v) : lc;     // target: -log(sig(v) + eps)
            }
        }
    }

    // ---- reduction: warp f32 -> block f64 -> global atomic f64 ----
    const int lane = tid & 31, wid = tid >> 5;
    #pragma unroll
    for (int o = 16; o > 0; o >>= 1) loss += __shfl_down_sync(0xffffffffu, loss, o);
    if (lane == 0) ws[wid] = (double)loss;
    __syncthreads();
    if (wid == 0) {
        double v = (lane < TPB / 32) ? ws[lane] : 0.0;
        #pragma unroll
        for (int o = 4; o > 0; o >>= 1) v += __shfl_down_sync(0xffffffffu, v, o);
        if (lane == 0) {
            atomicAdd(&g_acc, v);
            __threadfence();
            unsigned done = atomicInc(&g_cnt, 0xffffffffu);
            if (done == (unsigned)(nBlocksTotal - 1)) {
                __threadfence();
                out[0] = (float)(*((volatile double*)&g_acc));
                g_acc = 0.0;                       // reset for next graph replay
                g_cnt = 0u;
            }
        }
    }
}

extern "C" void kernel_launch(void* const* d_in, const int* in_sizes, int n_in,
                              void* d_out, int out_size) {
    const float* x      = (const float*)d_in[0];
    const float* target = (const float*)d_in[1];
    const void*  dimp   = (n_in > 2) ? d_in[2] : nullptr;

    int nB = in_sizes[0] / (NA * NATTR * NH * NW);
    if (nB < 1) nB = 1;
    int nT = in_sizes[1] / (nB * 5);
    if (nT > MAXT) nT = MAXT;
    if (nT < 1) nT = 1;

    dim3 grid(BLKX, nB);
    yolo_fused<<<grid, TPB>>>(x, target, dimp, nT, (float*)d_out,
                              (int)(BLKX * nB));
}

// round 5
// speedup vs baseline: 2.3659x; 1.1082x over previous
#include <cuda_runtime.h>
#include <math.h>

#define NH 76
#define NW 76
#define NA 3
#define NCLS 80
#define NATTR 85
#define MAXT 64
#define CELLS (NA * NH * NW)   // 17328
#define HW (NH * NW)           // 5776
#define TPB 256
#define CPB (2 * TPB)          // cells per block = 512
#define BLKX ((CELLS + CPB - 1) / CPB)   // 34

__device__ double   g_acc;
__device__ unsigned g_cnt;

__constant__ float c_anch[18] = {10.f,13.f, 16.f,30.f, 33.f,23.f, 30.f,61.f, 62.f,45.f,
                                 59.f,119.f, 116.f,90.f, 156.f,198.f, 373.f,326.f};

__device__ __forceinline__ float read_dim(const void* p) {
    if (p == nullptr) return 608.0f;
    int iv = *(const int*)p;
    if (iv > 0 && iv < 1000000) return (float)iv;
    float fv = *(const float*)p;
    if (fv >= 1.0f && fv < 1.0e6f) return fv;
    return 608.0f;
}

struct Cell {
    float ax1, ax2, ay1, ay2;   // pred box corners
    float base;                  // (7/17)*(areaA + eps)
    float sx, sy, x2, x3, softp, x4;
    const float* xb;
    int cell;
};

__device__ __forceinline__ void cell_prologue(Cell& C, int cell, const float* __restrict__ x,
                                              int b, float invs) {
    C.cell = cell;
    const int a   = cell / HW;
    const int rem = cell - a * HW;
    const int j = rem / NW, i = rem - j * NW;

    const float* xb = x + ((size_t)b * (NA * NATTR) + (size_t)a * NATTR) * HW + rem;
    C.xb = xb;
    const float x0 = xb[0];
    const float x1 = xb[(size_t)HW];
    C.x2 = xb[2 * (size_t)HW];
    C.x3 = xb[3 * (size_t)HW];
    C.x4 = xb[4 * (size_t)HW];

    const float aw = c_anch[2*a] * invs, ah = c_anch[2*a+1] * invs;
    C.sx = __fdividef(1.0f, 1.0f + __expf(-x0));
    C.sy = __fdividef(1.0f, 1.0f + __expf(-x1));
    const float pw = __expf(C.x2) * aw, ph = __expf(C.x3) * ah;
    const float cx = C.sx + (float)i, cy = C.sy + (float)j;
    C.ax1 = cx - 0.5f * pw; C.ax2 = cx + 0.5f * pw;
    C.ay1 = cy - 0.5f * ph; C.ay2 = cy + 0.5f * ph;
    C.base = (7.0f / 17.0f) * (pw * ph + 1e-16f);
    C.softp = __logf(1.0f + __expf(C.x4));
}

__global__ void __launch_bounds__(TPB, 4)
yolo_fused(const float* __restrict__ x, const float* __restrict__ target,
           const void* dimp, int nT, float* __restrict__ out, int nBlocksTotal)
{
    __shared__ float4 s_box[MAXT];                 // bx1, by1, bx2, by2
    __shared__ float  s_kb[MAXT];                  // (7/17) * areaB
    __shared__ float  s_tx[MAXT], s_ty[MAXT], s_tw[MAXT], s_th[MAXT], s_m2[MAXT];
    __shared__ int    s_cls[MAXT], s_nz[MAXT];
    __shared__ int    s_win[CPB];
    __shared__ int    s_V;
    __shared__ double ws[TPB / 32];

    const int b   = blockIdx.y;
    const int tid = threadIdx.x;
    const int blockStart = blockIdx.x * CPB;
    const float img  = read_dim(dimp);
    const float invs = (float)NH / img;            // 1/stride

    s_win[tid] = -1;
    s_win[tid + TPB] = -1;

    // ---- per-block GT precompute (redundant across blocks; cheap) ----
    float t0 = 0.f, t1 = 0.f, t2 = 0.f, t3 = 0.f, t4 = 0.f;
    if (tid < nT) {
        const float* tg = target + ((size_t)b * nT + tid) * 5;
        t0 = tg[0]; t1 = tg[1]; t2 = tg[2]; t3 = tg[3]; t4 = tg[4];
        s_nz[tid] = ((t0 + t1 + t2 + t3 + t4) != 0.0f) ? 1 : 0;
    }
    __syncthreads();
    if (tid == 0) {                                // validity = cumprod => prefix length
        int V = 0;
        while (V < nT && s_nz[V]) V++;
        s_V = V;
    }
    __syncthreads();

    if (tid < s_V) {                               // only valid GTs participate
        float gx = t1 * NW, gy = t2 * NH, gw = t3 * NW, gh = t4 * NH;
        int gi = min(max((int)gx, 0), NW - 1);
        int gj = min(max((int)gy, 0), NH - 1);

        int best = 0; float bestr = -1.0f;
        #pragma unroll
        for (int k = 0; k < 9; k++) {
            float aw = c_anch[2*k] * invs, ah = c_anch[2*k+1] * invs;
            float inter = fminf(gw, aw) * fminf(gh, ah);
            float uni   = gw * gh + aw * ah - inter;
            float r = __fdividef(inter, uni + 1e-16f);
            if (r > bestr) { bestr = r; best = k; }
        }
        int aloc = (best < NA) ? best : -1;        // mask = [0,1,2]

        s_box[tid] = make_float4(gx - 0.5f * gw, gy - 0.5f * gh,
                                 gx + 0.5f * gw, gy + 0.5f * gh);
        s_kb[tid]  = (7.0f / 17.0f) * (gw * gh);
        s_tx[tid] = gx - (float)gi;
        s_ty[tid] = gy - (float)gj;
        int al = max(aloc, 0);
        s_tw[tid] = __logf(__fdividef(gw, c_anch[2*al]   * invs) + 1e-16f);
        s_th[tid] = __logf(__fdividef(gh, c_anch[2*al+1] * invs) + 1e-16f);
        s_m2[tid] = 2.0f - t3 * t4;                // coord^2
        s_cls[tid] = min(max((int)t0, 0), NCLS - 1);

        if (aloc >= 0) {
            int cellid = aloc * HW + gj * NW + gi;
            int idx = cellid - blockStart;
            if (idx >= 0 && idx < CPB)
                atomicMax(&s_win[idx], tid);       // max-t == last-t-wins scatter
        }
    }
    __syncthreads();

    // ---- per-cell loss: 2 cells per thread ----
    const int cell0 = blockStart + tid;
    const int cell1 = blockStart + TPB + tid;
    const bool ok0 = (cell0 < CELLS);
    const bool ok1 = (cell1 < CELLS);

    Cell C0, C1;
    if (ok0) cell_prologue(C0, cell0, x, b, invs);
    if (ok1) cell_prologue(C1, cell1, x, b, invs);

    const int V = s_V;
    float ign0 = -3.0e38f, ign1 = -3.0e38f;
    #pragma unroll 4
    for (int t = 0; t < V; t++) {
        const float4 bb = s_box[t];
        const float kb = s_kb[t];
        {   // cell 0
            float iw = fmaxf(fminf(C0.ax2, bb.z) - fmaxf(C0.ax1, bb.x), 0.0f);
            float ih = fminf(C0.ay2, bb.w) - fmaxf(C0.ay1, bb.y);
            ign0 = fmaxf(ign0, fmaf(iw, ih, -kb));   // (inter - kb); compare vs base later
        }
        {   // cell 1
            float iw = fmaxf(fminf(C1.ax2, bb.z) - fmaxf(C1.ax1, bb.x), 0.0f);
            float ih = fminf(C1.ay2, bb.w) - fmaxf(C1.ay1, bb.y);
            ign1 = fmaxf(ign1, fmaf(iw, ih, -kb));
        }
    }

    float loss = 0.0f;
    #pragma unroll
    for (int half = 0; half < 2; half++) {
        const bool ok = half ? ok1 : ok0;
        if (!ok) continue;
        const Cell& C = half ? C1 : C0;
        const float ign = half ? ign1 : ign0;

        if (!(ign > C.base)) loss += C.softp;      // noobj BCE term

        const int win = s_win[tid + half * TPB];
        if (win >= 0) {
            loss += C.softp - C.x4;                // -log(sigmoid(x4))
            const float dx = C.sx - s_tx[win], dy = C.sy - s_ty[win];
            const float dw = C.x2 - s_tw[win], dh = C.x3 - s_th[win];
            loss += 0.5f * s_m2[win] * (dx*dx + dy*dy + dw*dw + dh*dh);
            const int cc = s_cls[win];
            #pragma unroll 4
            for (int c = 0; c < NCLS; c++) {
                const float v = C.xb[(size_t)(5 + c) * HW];
                float lc = __logf(1.0f + __expf(v));   // -log(1 - sig(v) + eps)
                loss += (c == cc) ? (lc - v) : lc;     // -log(sig(v) + eps)
            }
        }
    }

    // ---- reduction: warp f32 -> block f64 -> global atomic f64 ----
    const int lane = tid & 31, wid = tid >> 5;
    #pragma unroll
    for (int o = 16; o > 0; o >>= 1) loss += __shfl_down_sync(0xffffffffu, loss, o);
    if (lane == 0) ws[wid] = (double)loss;
    __syncthreads();
    if (wid == 0) {
        double v = (lane < TPB / 32) ? ws[lane] : 0.0;
        #pragma unroll
        for (int o = 4; o > 0; o >>= 1) v += __shfl_down_sync(0xffffffffu, v, o);
        if (lane == 0) {
            atomicAdd(&g_acc, v);
            __threadfence();
            unsigned done = atomicInc(&g_cnt, 0xffffffffu);
            if (done == (unsigned)(nBlocksTotal - 1)) {
                __threadfence();
                out[0] = (float)(*((volatile double*)&g_acc));
                g_acc = 0.0;                       // reset for next graph replay
                g_cnt = 0u;
            }
        }
    }
}

extern "C" void kernel_launch(void* const* d_in, const int* in_sizes, int n_in,
                              void* d_out, int out_size) {
    const float* x      = (const float*)d_in[0];
    const float* target = (const float*)d_in[1];
    const void*  dimp   = (n_in > 2) ? d_in[2] : nullptr;

    int nB = in_sizes[0] / (NA * NATTR * NH * NW);
    if (nB < 1) nB = 1;
    int nT = in_sizes[1] / (nB * 5);
    if (nT > MAXT) nT = MAXT;
    if (nT < 1) nT = 1;

    dim3 grid(BLKX, nB);
    yolo_fused<<<grid, TPB>>>(x, target, dimp, nT, (float*)d_out,
                              (int)(BLKX * nB));
}